// round 12
// baseline (speedup 1.0000x reference)
#include <cuda_runtime.h>
#include <cstdint>

#define THREADS 256
#define ROWS_PER_BLOCK 128   // 8 warps x 16 rows each
#define P 20                 // pitch (words): conflict-free for all access patterns

// ---- smem word offsets ----
#define W_O     0                          // fp16x2 pairs: [k][nrow*P + pair]
#define W_WORDS (16 * 24 * P)              // 7680
#define SLAB_O  W_WORDS                    // ov slab fp16x2: [row*P + pair], 128 rows
#define SLAB_WORDS (ROWS_PER_BLOCK * P)    // 2560
#define WOUT_O  (SLAB_O + SLAB_WORDS)      // 24*3 f32
#define BOUT_O  (WOUT_O + 72)
#define SMEM_WORDS (BOUT_O + 4)            // 10316 words = 41,264 B -> 3 CTAs/SM

// ---- fast transcendentals (MUFU pipe) ----
__device__ __forceinline__ float softplus_fast(float x) {
    float e, l;
    float y = fabsf(x) * -1.4426950408889634f;
    asm("ex2.approx.f32 %0, %1;" : "=f"(e) : "f"(y));
    float u = 1.0f + e;
    asm("lg2.approx.f32 %0, %1;" : "=f"(l) : "f"(u));
    return fmaxf(x, 0.0f) + l * 0.6931471805599453f;
}
__device__ __forceinline__ float exp_fast(float x) {
    float e;
    asm("ex2.approx.f32 %0, %1;" : "=f"(e) : "f"(x * 1.4426950408889634f));
    return e;
}
__device__ __forceinline__ float rcp_fast(float x) {
    float r;
    asm("rcp.approx.f32 %0, %1;" : "=f"(r) : "f"(x));
    return r;
}

// pack two f32 -> f16x2 {hi=vh, lo=vl}
#define PACK_F16X2(d, vh, vl) \
    asm("cvt.rn.f16x2.f32 %0, %1, %2;" : "=r"(d) : "f"(vh), "f"(vl))

// m16n8k16 fp16 MMA, f32 accumulate in place
__device__ __forceinline__ void mma_f16(float* d, const uint32_t* a,
                                        uint32_t b0, uint32_t b1) {
    asm volatile(
        "mma.sync.aligned.m16n8k16.row.col.f32.f16.f16.f32 "
        "{%0,%1,%2,%3}, {%4,%5,%6,%7}, {%8,%9}, {%0,%1,%2,%3};"
        : "+f"(d[0]), "+f"(d[1]), "+f"(d[2]), "+f"(d[3])
        : "r"(a[0]), "r"(a[1]), "r"(a[2]), "r"(a[3]), "r"(b0), "r"(b1));
}

#define LDMATRIX_X4(a, addr) \
    asm volatile("ldmatrix.sync.aligned.m8n8.x4.shared.b16 {%0,%1,%2,%3}, [%4];" \
        : "=r"((a)[0]), "=r"((a)[1]), "=r"((a)[2]), "=r"((a)[3]) : "r"(addr))

__device__ __forceinline__ uint32_t smem_u32(const void* p) {
    uint32_t a;
    asm("{ .reg .u64 t; cvta.to.shared.u64 t, %1; cvt.u32.u64 %0, t; }" : "=r"(a) : "l"(p));
    return a;
}

// V element for (global row, col)
__device__ __forceinline__ float v_col(const float* __restrict__ xr, int col,
                                       float bt, float bc,
                                       float a1, float a2, float a3) {
    if (col < 19) return __ldg(&xr[col]);
    if (col == 19) return __ldg(&xr[21]);
    if (col == 20) return __ldg(&xr[24]);
    if (col == 21) return fmaf(bc, __ldg(&xr[20]), fmaf(bt, __ldg(&xr[19]), a1));
    if (col == 22) return fmaf(bc, __ldg(&xr[23]), fmaf(bt, __ldg(&xr[22]), a2));
    return fmaf(bc, __ldg(&xr[26]), fmaf(bt, __ldg(&xr[25]), a3));
}

__global__ __launch_bounds__(THREADS, 3)
void reslogit_f16_kernel(const float* __restrict__ x,
                         const float* __restrict__ asc_train,
                         const float* __restrict__ asc_sm,
                         const float* __restrict__ asc_car,
                         const float* __restrict__ b_time,
                         const float* __restrict__ b_cost,
                         const float* __restrict__ Ws,
                         const float* __restrict__ W_out,
                         const float* __restrict__ b_out,
                         float* __restrict__ out,
                         int B)
{
    extern __shared__ uint32_t sm[];
    float* smf   = reinterpret_cast<float*>(sm);
    uint32_t* Wp = sm + W_O;
    uint32_t* sl = sm + SLAB_O;
    float* sWout = smf + WOUT_O;
    float* sbout = smf + BOUT_O;

    const int tid  = threadIdx.x;
    const int row0 = blockIdx.x * ROWS_PER_BLOCK;

    // ---- zero ov slab (pads beyond pair 11 stay 0) ----
    for (int i = tid; i < SLAB_WORDS; i += THREADS) sl[i] = 0u;
    if (tid < 72) sWout[tid] = W_out[tid];
    if (tid < 3)  sbout[tid] = b_out[tid];

    // ---- stage W as fp16 k-pairs, B-operand (col-major-K) layout ----
    for (int idx = tid; idx < 16 * 24 * 16; idx += THREADS) {
        const int k = idx / 384, rem = idx % 384;
        const int nrow = rem / 16, p = rem % 16;
        const int r0 = 2 * p, r1 = 2 * p + 1;
        const float v0 = (r0 < 24) ? __ldg(&Ws[k * 576 + r0 * 24 + nrow]) : 0.0f;
        const float v1 = (r1 < 24) ? __ldg(&Ws[k * 576 + r1 * 24 + nrow]) : 0.0f;
        uint32_t h;  PACK_F16X2(h, v1, v0);
        Wp[k * (24 * P) + nrow * P + p] = h;
    }
    __syncthreads();

    const int lane  = tid & 31;
    const int g     = lane >> 2;        // groupID
    const int t     = lane & 3;         // thread-in-group
    const int wbase = (tid >> 5) * 16;  // warp's 16-row tile base

    const float bt = __ldg(b_time), bc = __ldg(b_cost);
    const float a1 = __ldg(asc_train), a2 = __ldg(asc_sm), a3 = __ldg(asc_car);

    // thread's 2 rows (local): g and g+8 within the warp tile
    const int rloc0 = wbase + g, rloc1 = wbase + g + 8;

    // global x row pointers (clamped on tail; outputs guarded later)
    const float* xp[2];
    {
        int r = row0 + rloc0; if (r >= B) r = B - 1;
        xp[0] = x + (size_t)r * 27;
        r = row0 + rloc1; if (r >= B) r = B - 1;
        xp[1] = x + (size_t)r * 27;
    }

    // ldmatrix per-lane addresses for ch = 0,1 (k-invariant)
    const uint32_t sbase = smem_u32(sm);
    uint32_t lm_addr[2];
    {
        const int tile = lane >> 3, rit = lane & 7;
        #pragma unroll
        for (int ch = 0; ch < 2; ch++) {
            const int row  = wbase + (tile & 1) * 8 + rit;
            const int word = SLAB_O + row * P + ch * 8 + (tile >> 1) * 4;
            lm_addr[ch] = sbase + word * 4;
        }
    }

    // state in C-fragment patch layout: c0,c1 -> row rloc0; c2,c3 -> row rloc1; col = 8n+2t+(c&1)
    float ov[3][4], S[3][4];
    #pragma unroll
    for (int n = 0; n < 3; n++)
        #pragma unroll
        for (int c = 0; c < 4; c++) {
            ov[n][c] = v_col(xp[c >> 1], 8 * n + 2 * t + (c & 1), bt, bc, a1, a2, a3);
            S[n][c] = 0.0f;
        }

    // publish ov (fp16 pairs) to slab
    auto publish = [&]() {
        #pragma unroll
        for (int n = 0; n < 3; n++)
            #pragma unroll
            for (int s = 0; s < 2; s++) {
                const int row = s ? rloc1 : rloc0;
                uint32_t h;
                PACK_F16X2(h, ov[n][s * 2 + 1], ov[n][s * 2 + 0]);
                sl[row * P + 4 * n + t] = h;
            }
    };
    publish();
    __syncwarp();

    // ---- 16-step scan ----
    #pragma unroll 1
    for (int k = 0; k < 16; k++) {
        const uint32_t* Wk = Wp + k * (24 * P);

        float D[3][4];
        #pragma unroll
        for (int n = 0; n < 3; n++)
            #pragma unroll
            for (int c = 0; c < 4; c++) D[n][c] = 0.0f;

        #pragma unroll
        for (int ch = 0; ch < 2; ch++) {
            uint32_t a[4];
            LDMATRIX_X4(a, lm_addr[ch]);
            #pragma unroll
            for (int n = 0; n < 3; n++) {
                const int bi = (8 * n + g) * P + ch * 8 + t;
                mma_f16(D[n], a, Wk[bi], Wk[bi + 4]);
            }
        }
        __syncwarp();

        // softplus + running-sum scan update (ov_k = ov_{k-1} - S_k)
        #pragma unroll
        for (int n = 0; n < 3; n++)
            #pragma unroll
            for (int c = 0; c < 4; c++) {
                S[n][c] += softplus_fast(D[n][c]);
                ov[n][c] -= S[n][c];
            }

        if (k < 15) {
            publish();
            __syncwarp();
        }
    }

    // ---- epilogue: U = V - S_16, softmax(24), @W_out + b_out, relu ----
    float u[3][4];
    #pragma unroll
    for (int n = 0; n < 3; n++)
        #pragma unroll
        for (int c = 0; c < 4; c++)
            u[n][c] = v_col(xp[c >> 1], 8 * n + 2 * t + (c & 1), bt, bc, a1, a2, a3) - S[n][c];

    #pragma unroll
    for (int s = 0; s < 2; s++) {
        float mx = -3.4e38f;
        #pragma unroll
        for (int n = 0; n < 3; n++)
            #pragma unroll
            for (int p = 0; p < 2; p++) mx = fmaxf(mx, u[n][s * 2 + p]);
        mx = fmaxf(mx, __shfl_xor_sync(0xffffffffu, mx, 1));
        mx = fmaxf(mx, __shfl_xor_sync(0xffffffffu, mx, 2));

        float e[6], ssum = 0.0f;
        #pragma unroll
        for (int n = 0; n < 3; n++)
            #pragma unroll
            for (int p = 0; p < 2; p++) {
                const float ev = exp_fast(u[n][s * 2 + p] - mx);
                e[n * 2 + p] = ev;
                ssum += ev;
            }
        ssum += __shfl_xor_sync(0xffffffffu, ssum, 1);
        ssum += __shfl_xor_sync(0xffffffffu, ssum, 2);
        const float inv = rcp_fast(ssum);

        float d0 = 0.0f, d1 = 0.0f, d2 = 0.0f;
        #pragma unroll
        for (int n = 0; n < 3; n++)
            #pragma unroll
            for (int p = 0; p < 2; p++) {
                const int col = 8 * n + 2 * t + p;
                const float ev = e[n * 2 + p];
                d0 = fmaf(ev, sWout[col * 3 + 0], d0);
                d1 = fmaf(ev, sWout[col * 3 + 1], d1);
                d2 = fmaf(ev, sWout[col * 3 + 2], d2);
            }
        d0 += __shfl_xor_sync(0xffffffffu, d0, 1);
        d0 += __shfl_xor_sync(0xffffffffu, d0, 2);
        d1 += __shfl_xor_sync(0xffffffffu, d1, 1);
        d1 += __shfl_xor_sync(0xffffffffu, d1, 2);
        d2 += __shfl_xor_sync(0xffffffffu, d2, 1);
        d2 += __shfl_xor_sync(0xffffffffu, d2, 2);

        if (t == 0) {
            const int grow = row0 + (s ? rloc1 : rloc0);
            if (grow < B) {
                float* op = out + (size_t)grow * 3;
                op[0] = fmaxf(fmaf(d0, inv, sbout[0]), 0.0f);
                op[1] = fmaxf(fmaf(d1, inv, sbout[1]), 0.0f);
                op[2] = fmaxf(fmaf(d2, inv, sbout[2]), 0.0f);
            }
        }
    }
}

extern "C" void kernel_launch(void* const* d_in, const int* in_sizes, int n_in,
                              void* d_out, int out_size)
{
    const float* x         = (const float*)d_in[0];
    const float* asc_train = (const float*)d_in[1];
    const float* asc_sm    = (const float*)d_in[2];
    const float* asc_car   = (const float*)d_in[3];
    const float* b_time    = (const float*)d_in[4];
    const float* b_cost    = (const float*)d_in[5];
    const float* Ws        = (const float*)d_in[6];
    const float* W_out     = (const float*)d_in[7];
    const float* b_out     = (const float*)d_in[8];
    float* out = (float*)d_out;

    const int B = in_sizes[0] / 27;
    const int smem_bytes = SMEM_WORDS * 4;

    cudaFuncSetAttribute(reslogit_f16_kernel,
                         cudaFuncAttributeMaxDynamicSharedMemorySize, smem_bytes);

    const int grid = (B + ROWS_PER_BLOCK - 1) / ROWS_PER_BLOCK;
    reslogit_f16_kernel<<<grid, THREADS, smem_bytes>>>(
        x, asc_train, asc_sm, asc_car, b_time, b_cost, Ws, W_out, b_out, out, B);
}

// round 13
// speedup vs baseline: 1.0350x; 1.0350x over previous
#include <cuda_runtime.h>
#include <cstdint>

#define THREADS 256
#define ROWS_PER_BLOCK 256   // 8 warps x 32 rows
#define P 20                 // W pitch (words): conflict-free B-load pattern

// ---- smem word offsets ----
#define W_O     0                    // fp16x2 pairs: [k][nrow*P + pair]
#define W_WORDS (16 * 24 * P)        // 7680
#define WOUT_O  W_WORDS              // 24*3 f32
#define BOUT_O  (WOUT_O + 72)
#define SMEM_WORDS (BOUT_O + 4)      // 7756 words = 31,024 B

// ---- fast transcendentals (MUFU pipe) ----
__device__ __forceinline__ float softplus_fast(float x) {
    float e, l;
    float y = fabsf(x) * -1.4426950408889634f;
    asm("ex2.approx.f32 %0, %1;" : "=f"(e) : "f"(y));
    float u = 1.0f + e;
    asm("lg2.approx.f32 %0, %1;" : "=f"(l) : "f"(u));
    return fmaxf(x, 0.0f) + l * 0.6931471805599453f;
}
__device__ __forceinline__ float exp_fast(float x) {
    float e;
    asm("ex2.approx.f32 %0, %1;" : "=f"(e) : "f"(x * 1.4426950408889634f));
    return e;
}
__device__ __forceinline__ float rcp_fast(float x) {
    float r;
    asm("rcp.approx.f32 %0, %1;" : "=f"(r) : "f"(x));
    return r;
}

// pack two f32 -> f16x2 {hi=vh, lo=vl}
#define PACK_F16X2(d, vh, vl) \
    asm("cvt.rn.f16x2.f32 %0, %1, %2;" : "=r"(d) : "f"(vh), "f"(vl))

// m16n8k16 fp16 MMA, f32 accumulate in place
__device__ __forceinline__ void mma_f16(float* d, const uint32_t* a,
                                        uint32_t b0, uint32_t b1) {
    asm volatile(
        "mma.sync.aligned.m16n8k16.row.col.f32.f16.f16.f32 "
        "{%0,%1,%2,%3}, {%4,%5,%6,%7}, {%8,%9}, {%0,%1,%2,%3};"
        : "+f"(d[0]), "+f"(d[1]), "+f"(d[2]), "+f"(d[3])
        : "r"(a[0]), "r"(a[1]), "r"(a[2]), "r"(a[3]), "r"(b0), "r"(b1));
}

// V element for (global row, col)
__device__ __forceinline__ float v_col(const float* __restrict__ xr, int col,
                                       float bt, float bc,
                                       float a1, float a2, float a3) {
    if (col < 19) return __ldg(&xr[col]);
    if (col == 19) return __ldg(&xr[21]);
    if (col == 20) return __ldg(&xr[24]);
    if (col == 21) return fmaf(bc, __ldg(&xr[20]), fmaf(bt, __ldg(&xr[19]), a1));
    if (col == 22) return fmaf(bc, __ldg(&xr[23]), fmaf(bt, __ldg(&xr[22]), a2));
    return fmaf(bc, __ldg(&xr[26]), fmaf(bt, __ldg(&xr[25]), a3));
}

__global__ __launch_bounds__(THREADS, 2)
void reslogit_f16r_kernel(const float* __restrict__ x,
                          const float* __restrict__ asc_train,
                          const float* __restrict__ asc_sm,
                          const float* __restrict__ asc_car,
                          const float* __restrict__ b_time,
                          const float* __restrict__ b_cost,
                          const float* __restrict__ Ws,
                          const float* __restrict__ W_out,
                          const float* __restrict__ b_out,
                          float* __restrict__ out,
                          int B)
{
    extern __shared__ uint32_t sm[];
    float* smf   = reinterpret_cast<float*>(sm);
    uint32_t* Wp = sm + W_O;
    float* sWout = smf + WOUT_O;
    float* sbout = smf + BOUT_O;

    const int tid  = threadIdx.x;
    const int row0 = blockIdx.x * ROWS_PER_BLOCK;

    if (tid < 72) sWout[tid] = W_out[tid];
    if (tid < 3)  sbout[tid] = b_out[tid];

    // ---- stage W as fp16 k-pairs, B-operand (col-major-K) layout ----
    // Wp[k][nrow*P + p] = {hi=f16(W[k][2p+1][nrow]), lo=f16(W[k][2p][nrow])}, p>=12 -> 0
    for (int idx = tid; idx < 16 * 24 * 16; idx += THREADS) {
        const int k = idx / 384, rem = idx % 384;
        const int nrow = rem / 16, p = rem % 16;
        const int r0 = 2 * p, r1 = 2 * p + 1;
        const float v0 = (r0 < 24) ? __ldg(&Ws[k * 576 + r0 * 24 + nrow]) : 0.0f;
        const float v1 = (r1 < 24) ? __ldg(&Ws[k * 576 + r1 * 24 + nrow]) : 0.0f;
        uint32_t h;  PACK_F16X2(h, v1, v0);
        Wp[k * (24 * P) + nrow * P + p] = h;
    }
    __syncthreads();

    const int lane  = tid & 31;
    const int g     = lane >> 2;        // groupID
    const int t     = lane & 3;         // thread-in-group
    const int wbase = (tid >> 5) * 32;  // warp's 32-row tile base

    const float bt = __ldg(b_time), bc = __ldg(b_cost);
    const float a1 = __ldg(asc_train), a2 = __ldg(asc_sm), a3 = __ldg(asc_car);

    int rloc[4];
    rloc[0] = wbase + g;       rloc[1] = wbase + g + 8;
    rloc[2] = wbase + 16 + g;  rloc[3] = wbase + 24 + g;

    const float* xp[4];
    #pragma unroll
    for (int r = 0; r < 4; r++) {
        int grow = row0 + rloc[r];
        if (grow >= B) grow = B - 1;
        xp[r] = x + (size_t)grow * 27;
    }

    // state in C-fragment patch layout: row = rloc[m*2+(c>>1)], col = 8n+2t+(c&1)
    float ov[2][3][4], S[2][3][4];
    #pragma unroll
    for (int m = 0; m < 2; m++)
        #pragma unroll
        for (int n = 0; n < 3; n++)
            #pragma unroll
            for (int c = 0; c < 4; c++) {
                ov[m][n][c] = v_col(xp[m * 2 + (c >> 1)], 8 * n + 2 * t + (c & 1),
                                    bt, bc, a1, a2, a3);
                S[m][n][c] = 0.0f;
            }

    // per-thread B base: element (k-pair t) of n-row g
    const uint32_t* Wt = Wp + g * P + t;

    // ---- 16-step scan; ov never leaves registers ----
    // KEY IDENTITY: the C-fragment layout of ov doubles as the A-fragment
    // layout of the next MMA. k-chunk0 A-frag = {ov[n0] pairs, ov[n1] pairs};
    // k-chunk1 = {ov[n2] pairs, 0, 0} (cols 24..31 are zero).
    #pragma unroll 1
    for (int k = 0; k < 16; k++) {
        const uint32_t* Wk = Wt + k * 480;

        float D[2][3][4];
        #pragma unroll
        for (int m = 0; m < 2; m++)
            #pragma unroll
            for (int n = 0; n < 3; n++)
                #pragma unroll
                for (int c = 0; c < 4; c++) D[m][n][c] = 0.0f;

        #pragma unroll
        for (int ch = 0; ch < 2; ch++) {
            // A fragments straight from ov registers
            uint32_t A0[4], A1[4];
            if (ch == 0) {
                PACK_F16X2(A0[0], ov[0][0][1], ov[0][0][0]);
                PACK_F16X2(A0[1], ov[0][0][3], ov[0][0][2]);
                PACK_F16X2(A0[2], ov[0][1][1], ov[0][1][0]);
                PACK_F16X2(A0[3], ov[0][1][3], ov[0][1][2]);
                PACK_F16X2(A1[0], ov[1][0][1], ov[1][0][0]);
                PACK_F16X2(A1[1], ov[1][0][3], ov[1][0][2]);
                PACK_F16X2(A1[2], ov[1][1][1], ov[1][1][0]);
                PACK_F16X2(A1[3], ov[1][1][3], ov[1][1][2]);
            } else {
                PACK_F16X2(A0[0], ov[0][2][1], ov[0][2][0]);
                PACK_F16X2(A0[1], ov[0][2][3], ov[0][2][2]);
                A0[2] = 0u; A0[3] = 0u;
                PACK_F16X2(A1[0], ov[1][2][1], ov[1][2][0]);
                PACK_F16X2(A1[1], ov[1][2][3], ov[1][2][2]);
                A1[2] = 0u; A1[3] = 0u;
            }
            #pragma unroll
            for (int n = 0; n < 3; n++) {
                const uint32_t b0 = Wk[n * (8 * P) + ch * 8];
                const uint32_t b1 = Wk[n * (8 * P) + ch * 8 + 4];
                mma_f16(D[0][n], A0, b0, b1);
                mma_f16(D[1][n], A1, b0, b1);
            }
        }

        // softplus + running-sum scan update (ov_k = ov_{k-1} - S_k)
        #pragma unroll
        for (int m = 0; m < 2; m++)
            #pragma unroll
            for (int n = 0; n < 3; n++)
                #pragma unroll
                for (int c = 0; c < 4; c++) {
                    S[m][n][c] += softplus_fast(D[m][n][c]);
                    ov[m][n][c] -= S[m][n][c];
                }
    }

    // ---- epilogue: U = V - S_16, softmax(24), @W_out + b_out, relu ----
    float u[2][3][4];
    #pragma unroll
    for (int m = 0; m < 2; m++)
        #pragma unroll
        for (int n = 0; n < 3; n++)
            #pragma unroll
            for (int c = 0; c < 4; c++)
                u[m][n][c] = v_col(xp[m * 2 + (c >> 1)], 8 * n + 2 * t + (c & 1),
                                   bt, bc, a1, a2, a3) - S[m][n][c];

    #pragma unroll
    for (int rr = 0; rr < 4; rr++) {
        const int m = rr >> 1, ch = rr & 1;

        float mx = -3.4e38f;
        #pragma unroll
        for (int n = 0; n < 3; n++)
            #pragma unroll
            for (int p = 0; p < 2; p++) mx = fmaxf(mx, u[m][n][ch * 2 + p]);
        mx = fmaxf(mx, __shfl_xor_sync(0xffffffffu, mx, 1));
        mx = fmaxf(mx, __shfl_xor_sync(0xffffffffu, mx, 2));

        float e[6], s = 0.0f;
        #pragma unroll
        for (int n = 0; n < 3; n++)
            #pragma unroll
            for (int p = 0; p < 2; p++) {
                const float ev = exp_fast(u[m][n][ch * 2 + p] - mx);
                e[n * 2 + p] = ev;
                s += ev;
            }
        s += __shfl_xor_sync(0xffffffffu, s, 1);
        s += __shfl_xor_sync(0xffffffffu, s, 2);
        const float inv = rcp_fast(s);

        float d0 = 0.0f, d1 = 0.0f, d2 = 0.0f;
        #pragma unroll
        for (int n = 0; n < 3; n++)
            #pragma unroll
            for (int p = 0; p < 2; p++) {
                const int col = 8 * n + 2 * t + p;
                const float ev = e[n * 2 + p];
                d0 = fmaf(ev, sWout[col * 3 + 0], d0);
                d1 = fmaf(ev, sWout[col * 3 + 1], d1);
                d2 = fmaf(ev, sWout[col * 3 + 2], d2);
            }
        d0 += __shfl_xor_sync(0xffffffffu, d0, 1);
        d0 += __shfl_xor_sync(0xffffffffu, d0, 2);
        d1 += __shfl_xor_sync(0xffffffffu, d1, 1);
        d1 += __shfl_xor_sync(0xffffffffu, d1, 2);
        d2 += __shfl_xor_sync(0xffffffffu, d2, 1);
        d2 += __shfl_xor_sync(0xffffffffu, d2, 2);

        if (t == 0) {
            const int grow = row0 + rloc[rr];
            if (grow < B) {
                float* op = out + (size_t)grow * 3;
                op[0] = fmaxf(fmaf(d0, inv, sbout[0]), 0.0f);
                op[1] = fmaxf(fmaf(d1, inv, sbout[1]), 0.0f);
                op[2] = fmaxf(fmaf(d2, inv, sbout[2]), 0.0f);
            }
        }
    }
}

extern "C" void kernel_launch(void* const* d_in, const int* in_sizes, int n_in,
                              void* d_out, int out_size)
{
    const float* x         = (const float*)d_in[0];
    const float* asc_train = (const float*)d_in[1];
    const float* asc_sm    = (const float*)d_in[2];
    const float* asc_car   = (const float*)d_in[3];
    const float* b_time    = (const float*)d_in[4];
    const float* b_cost    = (const float*)d_in[5];
    const float* Ws        = (const float*)d_in[6];
    const float* W_out     = (const float*)d_in[7];
    const float* b_out     = (const float*)d_in[8];
    float* out = (float*)d_out;

    const int B = in_sizes[0] / 27;
    const int smem_bytes = SMEM_WORDS * 4;

    cudaFuncSetAttribute(reslogit_f16r_kernel,
                         cudaFuncAttributeMaxDynamicSharedMemorySize, smem_bytes);

    const int grid = (B + ROWS_PER_BLOCK - 1) / ROWS_PER_BLOCK;
    reslogit_f16r_kernel<<<grid, THREADS, smem_bytes>>>(
        x, asc_train, asc_sm, asc_car, b_time, b_cost, Ws, W_out, b_out, out, B);
}

// round 14
// speedup vs baseline: 1.0775x; 1.0410x over previous
#include <cuda_runtime.h>
#include <cstdint>

#define THREADS 256
#define ROWS_PER_BLOCK 256   // 8 warps x 32 rows
#define P 20                 // W pitch (words): conflict-free B-load pattern

// ---- smem word offsets ----
#define W_O     0                    // fp16x2 pairs: [k][nrow*P + pair]
#define W_WORDS (16 * 24 * P)        // 7680
#define WOUT_O  W_WORDS              // 24*3 f32
#define BOUT_O  (WOUT_O + 72)
#define SMEM_WORDS (BOUT_O + 4)      // 31,024 B

// ---- fast transcendentals (MUFU pipe) ----
__device__ __forceinline__ float softplus_fast(float x) {
    float e, l;
    float y = fabsf(x) * -1.4426950408889634f;
    asm("ex2.approx.f32 %0, %1;" : "=f"(e) : "f"(y));
    float u = 1.0f + e;
    asm("lg2.approx.f32 %0, %1;" : "=f"(l) : "f"(u));
    return fmaxf(x, 0.0f) + l * 0.6931471805599453f;
}
__device__ __forceinline__ float exp_fast(float x) {
    float e;
    asm("ex2.approx.f32 %0, %1;" : "=f"(e) : "f"(x * 1.4426950408889634f));
    return e;
}
__device__ __forceinline__ float rcp_fast(float x) {
    float r;
    asm("rcp.approx.f32 %0, %1;" : "=f"(r) : "f"(x));
    return r;
}

#define PACK_F16X2(d, vh, vl) \
    asm("cvt.rn.f16x2.f32 %0, %1, %2;" : "=r"(d) : "f"(vh), "f"(vl))

// m16n8k16 fp16 MMA, accumulate in place
__device__ __forceinline__ void mma_acc(float* d, uint32_t a0, uint32_t a1,
                                        uint32_t a2, uint32_t a3,
                                        uint32_t b0, uint32_t b1) {
    asm volatile(
        "mma.sync.aligned.m16n8k16.row.col.f32.f16.f16.f32 "
        "{%0,%1,%2,%3}, {%4,%5,%6,%7}, {%8,%9}, {%0,%1,%2,%3};"
        : "+f"(d[0]), "+f"(d[1]), "+f"(d[2]), "+f"(d[3])
        : "r"(a0), "r"(a1), "r"(a2), "r"(a3), "r"(b0), "r"(b1));
}
// first-chunk MMA: C = 0 (no D pre-zeroing)
__device__ __forceinline__ void mma_z(float* d, uint32_t a0, uint32_t a1,
                                      uint32_t a2, uint32_t a3,
                                      uint32_t b0, uint32_t b1) {
    asm volatile(
        "mma.sync.aligned.m16n8k16.row.col.f32.f16.f16.f32 "
        "{%0,%1,%2,%3}, {%4,%5,%6,%7}, {%8,%9}, {%10,%10,%10,%10};"
        : "=f"(d[0]), "=f"(d[1]), "=f"(d[2]), "=f"(d[3])
        : "r"(a0), "r"(a1), "r"(a2), "r"(a3), "r"(b0), "r"(b1), "f"(0.0f));
}

// V element for (global row, col)
__device__ __forceinline__ float v_col(const float* __restrict__ xr, int col,
                                       float bt, float bc,
                                       float a1, float a2, float a3) {
    if (col < 19) return __ldg(&xr[col]);
    if (col == 19) return __ldg(&xr[21]);
    if (col == 20) return __ldg(&xr[24]);
    if (col == 21) return fmaf(bc, __ldg(&xr[20]), fmaf(bt, __ldg(&xr[19]), a1));
    if (col == 22) return fmaf(bc, __ldg(&xr[23]), fmaf(bt, __ldg(&xr[22]), a2));
    return fmaf(bc, __ldg(&xr[26]), fmaf(bt, __ldg(&xr[25]), a3));
}

__global__ __launch_bounds__(THREADS, 2)
void reslogit_pipe_kernel(const float* __restrict__ x,
                          const float* __restrict__ asc_train,
                          const float* __restrict__ asc_sm,
                          const float* __restrict__ asc_car,
                          const float* __restrict__ b_time,
                          const float* __restrict__ b_cost,
                          const float* __restrict__ Ws,
                          const float* __restrict__ W_out,
                          const float* __restrict__ b_out,
                          float* __restrict__ out,
                          int B)
{
    extern __shared__ uint32_t sm[];
    float* smf   = reinterpret_cast<float*>(sm);
    uint32_t* Wp = sm + W_O;
    float* sWout = smf + WOUT_O;
    float* sbout = smf + BOUT_O;

    const int tid  = threadIdx.x;
    const int row0 = blockIdx.x * ROWS_PER_BLOCK;

    if (tid < 72) sWout[tid] = W_out[tid];
    if (tid < 3)  sbout[tid] = b_out[tid];

    // stage W as fp16 k-pairs, B-operand layout (verified in R11/R13)
    for (int idx = tid; idx < 16 * 24 * 16; idx += THREADS) {
        const int k = idx / 384, rem = idx % 384;
        const int nrow = rem / 16, p = rem % 16;
        const int r0 = 2 * p, r1 = 2 * p + 1;
        const float v0 = (r0 < 24) ? __ldg(&Ws[k * 576 + r0 * 24 + nrow]) : 0.0f;
        const float v1 = (r1 < 24) ? __ldg(&Ws[k * 576 + r1 * 24 + nrow]) : 0.0f;
        uint32_t h;  PACK_F16X2(h, v1, v0);
        Wp[k * (24 * P) + nrow * P + p] = h;
    }
    __syncthreads();

    const int lane  = tid & 31;
    const int g     = lane >> 2;
    const int t     = lane & 3;
    const int wbase = (tid >> 5) * 32;

    const float bt = __ldg(b_time), bc = __ldg(b_cost);
    const float a1 = __ldg(asc_train), a2 = __ldg(asc_sm), a3 = __ldg(asc_car);

    int rloc[4];
    rloc[0] = wbase + g;       rloc[1] = wbase + g + 8;
    rloc[2] = wbase + 16 + g;  rloc[3] = wbase + 24 + g;

    const float* xp[4];
    #pragma unroll
    for (int r = 0; r < 4; r++) {
        int grow = row0 + rloc[r];
        if (grow >= B) grow = B - 1;
        xp[r] = x + (size_t)grow * 27;
    }

    // state (C-fragment patch layout)
    float ov[2][3][4], S[2][3][4];
    #pragma unroll
    for (int m = 0; m < 2; m++)
        #pragma unroll
        for (int n = 0; n < 3; n++)
            #pragma unroll
            for (int c = 0; c < 4; c++) {
                ov[m][n][c] = v_col(xp[m * 2 + (c >> 1)], 8 * n + 2 * t + (c & 1),
                                    bt, bc, a1, a2, a3);
                S[m][n][c] = 0.0f;
            }

    const uint32_t* Wt = Wp + g * P + t;

    // A packs: P0[4] = k-chunk0 frag, P1[2] = k-chunk1 (upper halves zero)
    uint32_t P0m0[4], P1m0[2], P0m1[4], P1m1[2];
    uint32_t bb[12];   // B cache: [n][ch][j]

    auto packA = [&](int m, uint32_t* p0, uint32_t* p1) {
        PACK_F16X2(p0[0], ov[m][0][1], ov[m][0][0]);
        PACK_F16X2(p0[1], ov[m][0][3], ov[m][0][2]);
        PACK_F16X2(p0[2], ov[m][1][1], ov[m][1][0]);
        PACK_F16X2(p0[3], ov[m][1][3], ov[m][1][2]);
        PACK_F16X2(p1[0], ov[m][2][1], ov[m][2][0]);
        PACK_F16X2(p1[1], ov[m][2][3], ov[m][2][2]);
    };
    auto loadB = [&](int k) {
        const uint32_t* Wk = Wt + k * 480;
        #pragma unroll
        for (int n = 0; n < 3; n++)
            #pragma unroll
            for (int ch = 0; ch < 2; ch++) {
                bb[n * 4 + ch * 2 + 0] = Wk[n * (8 * P) + ch * 8];
                bb[n * 4 + ch * 2 + 1] = Wk[n * (8 * P) + ch * 8 + 4];
            }
    };
    auto mmaTile = [&](float* D, const uint32_t* p0, const uint32_t* p1) {
        #pragma unroll
        for (int n = 0; n < 3; n++)
            mma_z(D + 4 * n, p0[0], p0[1], p0[2], p0[3],
                  bb[n * 4 + 0], bb[n * 4 + 1]);
        #pragma unroll
        for (int n = 0; n < 3; n++)
            mma_acc(D + 4 * n, p1[0], p1[1], 0u, 0u,
                    bb[n * 4 + 2], bb[n * 4 + 3]);
    };
    auto spup = [&](int m, const float* D) {
        #pragma unroll
        for (int n = 0; n < 3; n++)
            #pragma unroll
            for (int c = 0; c < 4; c++) {
                S[m][n][c] += softplus_fast(D[4 * n + c]);
                ov[m][n][c] -= S[m][n][c];
            }
    };

    float D0[12], D1[12];

    // software pipeline: m0 runs half a step ahead of m1
    packA(0, P0m0, P1m0);
    packA(1, P0m1, P1m1);
    loadB(0);
    mmaTile(D0, P0m0, P1m0);                 // m0, k=0

    #pragma unroll 1
    for (int k = 0; k < 15; k++) {
        mmaTile(D1, P0m1, P1m1);             // m1, k   (B_k still cached)
        spup(0, D0);                         // softplus m0, k  (overlaps m1 MMAs)
        packA(0, P0m0, P1m0);
        loadB(k + 1);
        mmaTile(D0, P0m0, P1m0);             // m0, k+1
        spup(1, D1);                         // softplus m1, k  (overlaps m0 MMAs)
        packA(1, P0m1, P1m1);
    }
    mmaTile(D1, P0m1, P1m1);                 // m1, k=15
    spup(0, D0);                             // m0, k=15
    spup(1, D1);                             // m1, k=15

    // ---- epilogue: U = V - S_16, softmax(24), @W_out + b_out, relu ----
    float u[2][3][4];
    #pragma unroll
    for (int m = 0; m < 2; m++)
        #pragma unroll
        for (int n = 0; n < 3; n++)
            #pragma unroll
            for (int c = 0; c < 4; c++)
                u[m][n][c] = v_col(xp[m * 2 + (c >> 1)], 8 * n + 2 * t + (c & 1),
                                   bt, bc, a1, a2, a3) - S[m][n][c];

    #pragma unroll
    for (int rr = 0; rr < 4; rr++) {
        const int m = rr >> 1, ch = rr & 1;

        float mx = -3.4e38f;
        #pragma unroll
        for (int n = 0; n < 3; n++)
            #pragma unroll
            for (int p = 0; p < 2; p++) mx = fmaxf(mx, u[m][n][ch * 2 + p]);
        mx = fmaxf(mx, __shfl_xor_sync(0xffffffffu, mx, 1));
        mx = fmaxf(mx, __shfl_xor_sync(0xffffffffu, mx, 2));

        float e[6], s = 0.0f;
        #pragma unroll
        for (int n = 0; n < 3; n++)
            #pragma unroll
            for (int p = 0; p < 2; p++) {
                const float ev = exp_fast(u[m][n][ch * 2 + p] - mx);
                e[n * 2 + p] = ev;
                s += ev;
            }
        s += __shfl_xor_sync(0xffffffffu, s, 1);
        s += __shfl_xor_sync(0xffffffffu, s, 2);
        const float inv = rcp_fast(s);

        float d0 = 0.0f, d1 = 0.0f, d2 = 0.0f;
        #pragma unroll
        for (int n = 0; n < 3; n++)
            #pragma unroll
            for (int p = 0; p < 2; p++) {
                const int col = 8 * n + 2 * t + p;
                const float ev = e[n * 2 + p];
                d0 = fmaf(ev, sWout[col * 3 + 0], d0);
                d1 = fmaf(ev, sWout[col * 3 + 1], d1);
                d2 = fmaf(ev, sWout[col * 3 + 2], d2);
            }
        d0 += __shfl_xor_sync(0xffffffffu, d0, 1);
        d0 += __shfl_xor_sync(0xffffffffu, d0, 2);
        d1 += __shfl_xor_sync(0xffffffffu, d1, 1);
        d1 += __shfl_xor_sync(0xffffffffu, d1, 2);
        d2 += __shfl_xor_sync(0xffffffffu, d2, 1);
        d2 += __shfl_xor_sync(0xffffffffu, d2, 2);

        if (t == 0) {
            const int grow = row0 + rloc[rr];
            if (grow < B) {
                float* op = out + (size_t)grow * 3;
                op[0] = fmaxf(fmaf(d0, inv, sbout[0]), 0.0f);
                op[1] = fmaxf(fmaf(d1, inv, sbout[1]), 0.0f);
                op[2] = fmaxf(fmaf(d2, inv, sbout[2]), 0.0f);
            }
        }
    }
}

extern "C" void kernel_launch(void* const* d_in, const int* in_sizes, int n_in,
                              void* d_out, int out_size)
{
    const float* x         = (const float*)d_in[0];
    const float* asc_train = (const float*)d_in[1];
    const float* asc_sm    = (const float*)d_in[2];
    const float* asc_car   = (const float*)d_in[3];
    const float* b_time    = (const float*)d_in[4];
    const float* b_cost    = (const float*)d_in[5];
    const float* Ws        = (const float*)d_in[6];
    const float* W_out     = (const float*)d_in[7];
    const float* b_out     = (const float*)d_in[8];
    float* out = (float*)d_out;

    const int B = in_sizes[0] / 27;
    const int smem_bytes = SMEM_WORDS * 4;

    cudaFuncSetAttribute(reslogit_pipe_kernel,
                         cudaFuncAttributeMaxDynamicSharedMemorySize, smem_bytes);

    const int grid = (B + ROWS_PER_BLOCK - 1) / ROWS_PER_BLOCK;
    reslogit_pipe_kernel<<<grid, THREADS, smem_bytes>>>(
        x, asc_train, asc_sm, asc_car, b_time, b_cost, Ws, W_out, b_out, out, B);
}